// round 12
// baseline (speedup 1.0000x reference)
#include <cuda_runtime.h>
#include <cuda_bf16.h>
#include <cstdint>

#define N_NODES 100000
#define T_STEPS 12
#define THREADS 256
#define NODES_PER_CTA 128

// ---------- smem byte offsets ----------
#define SM_W0H 0          // 128 rows x 80B   (Whh0 hi, K=32)
#define SM_W0L 10240      // 128 rows x 80B   (Whh0 lo)
#define SM_W1H 20480      // 128 rows x 144B  ([Wih1|Whh1] hi, K=64)
#define SM_W1L 38912      // 128 rows x 144B  (lo)
#define SM_HBH 57344      // 128 nodes x 144B (h = [h0|h1] hi, K=64)
#define SM_HBL 75776      // 128 nodes x 144B (h lo)
#define SM_TSC 94208      // [12][128] f32
#define SM_SA0 100352     // 128 f
#define SM_SB0 100864     // 128 f
#define SM_SB1 101376     // 128 f
#define SM_FC1 101888     // 512 f
#define SM_FCB 103936     // bfc1[16] @ +0, wfc2[16] @ +64
#define SMEM_BYTES 104192 // -> 2 CTAs/SM

// ---------- helpers ----------
__device__ __forceinline__ float tanha(float x) {
    float t; asm("tanh.approx.f32 %0, %1;" : "=f"(t) : "f"(x)); return t;
}
__device__ __forceinline__ float siga(float x) { return fmaf(0.5f, tanha(0.5f * x), 0.5f); }

__device__ __forceinline__ uint32_t pk2(float a, float b) {
    __nv_bfloat162 t = __floats2bfloat162_rn(a, b);
    return *(uint32_t*)&t;
}
__device__ __forceinline__ void put_split(char* bh, char* bl, int off, float w) {
    __nv_bfloat16 h = __float2bfloat16(w);
    float r = w - __bfloat162float(h);
    __nv_bfloat16 l = __float2bfloat16(r);
    *(uint16_t*)(bh + off) = *(uint16_t*)&h;
    *(uint16_t*)(bl + off) = *(uint16_t*)&l;
}
// D += A(m16k16, row) x B(k16n8, col), bf16 -> f32
__device__ __forceinline__ void mma16816(float* d, const uint32_t* a, const uint32_t* b) {
    asm volatile("mma.sync.aligned.m16n8k16.row.col.f32.bf16.bf16.f32 "
                 "{%0,%1,%2,%3}, {%4,%5,%6,%7}, {%8,%9}, {%0,%1,%2,%3};"
                 : "+f"(d[0]), "+f"(d[1]), "+f"(d[2]), "+f"(d[3])
                 : "r"(a[0]), "r"(a[1]), "r"(a[2]), "r"(a[3]), "r"(b[0]), "r"(b[1]));
}

__global__ void __launch_bounds__(THREADS, 2)
lstm_hmma_kernel(const float* __restrict__ x,
                 const float* __restrict__ Wtp,  const float* __restrict__ btp,
                 const float* __restrict__ Wih0, const float* __restrict__ Whh0,
                 const float* __restrict__ bih0, const float* __restrict__ bhh0,
                 const float* __restrict__ Wih1, const float* __restrict__ Whh1,
                 const float* __restrict__ bih1, const float* __restrict__ bhh1,
                 const float* __restrict__ Wfc1, const float* __restrict__ bfc1,
                 const float* __restrict__ Wfc2, const float* __restrict__ bfc2,
                 float* __restrict__ out)
{
    extern __shared__ char smc[];
    float* sa0   = (float*)(smc + SM_SA0);
    float* sb0   = (float*)(smc + SM_SB0);
    float* sb1   = (float*)(smc + SM_SB1);
    float* sWfc1 = (float*)(smc + SM_FC1);
    float* sbfc1 = (float*)(smc + SM_FCB);
    float* sWfc2 = (float*)(smc + SM_FCB + 64);
    float* stsc  = (float*)(smc + SM_TSC);

    const int tid  = threadIdx.x;
    const int lane = tid & 31;
    const int warp = tid >> 5;
    const int gid  = lane >> 2;   // fragment group id (0..7)
    const int tig  = lane & 3;    // thread-in-group (0..3)
    const int NB   = warp * 16;   // this warp's node base (16 nodes per warp)

    // ---- weights -> bf16 hi/lo smem tiles ----
    for (int i = tid; i < 4096; i += THREADS) {
        int j = i >> 5, k = i & 31;
        put_split(smc + SM_W0H, smc + SM_W0L, j * 80 + k * 2,        Whh0[i]);
        put_split(smc + SM_W1H, smc + SM_W1L, j * 144 + k * 2,      Wih1[i]);
        put_split(smc + SM_W1H, smc + SM_W1L, j * 144 + 64 + k * 2, Whh1[i]);
    }
    // folded rank-1 input projection + biases  (tid == gate row, 0..127)
    if (tid < 128) {
        float a = 0.f, b = 0.f;
        #pragma unroll
        for (int j = 0; j < 16; j++) { float w = Wih0[tid * 16 + j]; a += w * Wtp[j]; b += w * btp[j]; }
        sa0[tid] = a;
        sb0[tid] = b + bih0[tid] + bhh0[tid];
        sb1[tid] = bih1[tid] + bhh1[tid];
    }
    for (int i = tid; i < 512; i += THREADS) sWfc1[i] = Wfc1[i];
    if (tid < 16) { sbfc1[tid] = bfc1[tid]; sWfc2[tid] = Wfc2[tid]; }

    // ---- temporal inputs to smem [s][node] (threads 0..127 own one node each) ----
    const int ng = blockIdx.x * NODES_PER_CTA + tid;   // valid for tid < 128
    if (tid < 128) {
        const int nc = (ng < N_NODES) ? ng : (N_NODES - 1);
        const float4* xp = (const float4*)(x + (size_t)nc * 64 + 52);
        float4 v0 = xp[0], v1 = xp[1], v2 = xp[2];
        float tv[12] = {v0.x,v0.y,v0.z,v0.w, v1.x,v1.y,v1.z,v1.w, v2.x,v2.y,v2.z,v2.w};
        #pragma unroll
        for (int s = 0; s < 12; s++) stsc[s * 128 + tid] = tv[s];
    }
    // ---- zero h buffers (h0 = h1 = 0) ----
    {
        uint4 z = {0, 0, 0, 0};
        uint4* p = (uint4*)(smc + SM_HBH);
        for (int i = tid; i < 2304; i += THREADS) p[i] = z;   // 36864 B
    }
    __syncthreads();

    // c-states in registers; index = njb*4 + rh*2 + e
    float c0[16], c1[16];
    #pragma unroll
    for (int i = 0; i < 16; i++) { c0[i] = 0.f; c1[i] = 0.f; }

    #pragma unroll 1
    for (int s = 0; s < T_STEPS; s++) {
        float tscm[2];
        #pragma unroll
        for (int rh = 0; rh < 2; rh++)
            tscm[rh] = stsc[s * 128 + NB + rh * 8 + gid];

        // ================= layer 0 : G = h0 @ Whh0^T  (K=32) =================
        uint32_t A0h[2][4], A0l[2][4];
        #pragma unroll
        for (int kt = 0; kt < 2; kt++) {
            int o = (NB + gid) * 144 + kt * 32 + tig * 4;
            A0h[kt][0] = *(uint32_t*)(smc + SM_HBH + o);
            A0h[kt][1] = *(uint32_t*)(smc + SM_HBH + o + 8 * 144);
            A0h[kt][2] = *(uint32_t*)(smc + SM_HBH + o + 16);
            A0h[kt][3] = *(uint32_t*)(smc + SM_HBH + o + 8 * 144 + 16);
            A0l[kt][0] = *(uint32_t*)(smc + SM_HBL + o);
            A0l[kt][1] = *(uint32_t*)(smc + SM_HBL + o + 8 * 144);
            A0l[kt][2] = *(uint32_t*)(smc + SM_HBL + o + 16);
            A0l[kt][3] = *(uint32_t*)(smc + SM_HBL + o + 8 * 144 + 16);
        }

        #pragma unroll
        for (int njb = 0; njb < 4; njb++) {
            float D[4][4];
            #pragma unroll
            for (int g = 0; g < 4; g++)
                #pragma unroll
                for (int e = 0; e < 2; e++) {
                    int n = njb * 8 + g * 32 + tig * 2 + e;
                    float sa = sa0[n], sv = sb0[n];
                    #pragma unroll
                    for (int rh = 0; rh < 2; rh++)
                        D[g][rh * 2 + e] = fmaf(tscm[rh], sa, sv);
                }
            #pragma unroll
            for (int g = 0; g < 4; g++) {
                int nb = (njb + g * 4) * 8;
                #pragma unroll
                for (int kt = 0; kt < 2; kt++) {
                    int o = (nb + gid) * 80 + kt * 32 + tig * 4;
                    uint32_t bh[2] = { *(uint32_t*)(smc + SM_W0H + o), *(uint32_t*)(smc + SM_W0H + o + 16) };
                    uint32_t bl[2] = { *(uint32_t*)(smc + SM_W0L + o), *(uint32_t*)(smc + SM_W0L + o + 16) };
                    mma16816(D[g], A0h[kt], bh);
                    mma16816(D[g], A0h[kt], bl);
                    mma16816(D[g], A0l[kt], bh);
                }
            }
            // epilogue: activations, c0 update, h0_new -> hbuf cols 0..31
            #pragma unroll
            for (int rh = 0; rh < 2; rh++) {
                float hv[2], hlo[2];
                #pragma unroll
                for (int e = 0; e < 2; e++) {
                    int idx = rh * 2 + e, ci = njb * 4 + rh * 2 + e;
                    float cn = siga(D[1][idx]) * c0[ci]
                             + siga(D[0][idx]) * tanha(D[2][idx]);
                    c0[ci] = cn;
                    float h = siga(D[3][idx]) * tanha(cn);
                    hv[e] = h;
                    hlo[e] = h - __bfloat162float(__float2bfloat16(h));
                }
                int o = (NB + rh * 8 + gid) * 144 + njb * 16 + tig * 4;
                *(uint32_t*)(smc + SM_HBH + o) = pk2(hv[0], hv[1]);
                *(uint32_t*)(smc + SM_HBL + o) = pk2(hlo[0], hlo[1]);
            }
        }
        __syncwarp();

        // ============ layer 1 : G = [h0new|h1] @ [Wih1|Whh1]^T  (K=64) ============
        uint32_t A1h[4][4], A1l[4][4];
        #pragma unroll
        for (int kt = 0; kt < 4; kt++) {
            int o = (NB + gid) * 144 + kt * 32 + tig * 4;
            A1h[kt][0] = *(uint32_t*)(smc + SM_HBH + o);
            A1h[kt][1] = *(uint32_t*)(smc + SM_HBH + o + 8 * 144);
            A1h[kt][2] = *(uint32_t*)(smc + SM_HBH + o + 16);
            A1h[kt][3] = *(uint32_t*)(smc + SM_HBH + o + 8 * 144 + 16);
            A1l[kt][0] = *(uint32_t*)(smc + SM_HBL + o);
            A1l[kt][1] = *(uint32_t*)(smc + SM_HBL + o + 8 * 144);
            A1l[kt][2] = *(uint32_t*)(smc + SM_HBL + o + 16);
            A1l[kt][3] = *(uint32_t*)(smc + SM_HBL + o + 8 * 144 + 16);
        }

        #pragma unroll
        for (int njb = 0; njb < 4; njb++) {
            float D[4][4];
            #pragma unroll
            for (int g = 0; g < 4; g++)
                #pragma unroll
                for (int e = 0; e < 2; e++) {
                    float sv = sb1[njb * 8 + g * 32 + tig * 2 + e];
                    D[g][e] = sv; D[g][2 + e] = sv;
                }
            #pragma unroll
            for (int g = 0; g < 4; g++) {
                int nb = (njb + g * 4) * 8;
                #pragma unroll
                for (int kt = 0; kt < 4; kt++) {
                    int o = (nb + gid) * 144 + kt * 32 + tig * 4;
                    uint32_t bh[2] = { *(uint32_t*)(smc + SM_W1H + o), *(uint32_t*)(smc + SM_W1H + o + 16) };
                    uint32_t bl[2] = { *(uint32_t*)(smc + SM_W1L + o), *(uint32_t*)(smc + SM_W1L + o + 16) };
                    mma16816(D[g], A1h[kt], bh);
                    mma16816(D[g], A1h[kt], bl);
                    mma16816(D[g], A1l[kt], bh);
                }
            }
            // epilogue: activations, c1 update, h1_new -> hbuf cols 32..63
            #pragma unroll
            for (int rh = 0; rh < 2; rh++) {
                float hv[2], hlo[2];
                #pragma unroll
                for (int e = 0; e < 2; e++) {
                    int idx = rh * 2 + e, ci = njb * 4 + rh * 2 + e;
                    float cn = siga(D[1][idx]) * c1[ci]
                             + siga(D[0][idx]) * tanha(D[2][idx]);
                    c1[ci] = cn;
                    float h = siga(D[3][idx]) * tanha(cn);
                    hv[e] = h;
                    hlo[e] = h - __bfloat162float(__float2bfloat16(h));
                }
                int o = (NB + rh * 8 + gid) * 144 + 64 + njb * 16 + tig * 4;
                *(uint32_t*)(smc + SM_HBH + o) = pk2(hv[0], hv[1]);
                *(uint32_t*)(smc + SM_HBL + o) = pk2(hlo[0], hlo[1]);
            }
        }
        __syncwarp();
    }

    // ---- FC head: thread tid (<128) = node tid; h1 written by warp tid/16 ----
    __syncthreads();
    if (tid < 128 && ng < N_NODES) {
        float h1f[32];
        #pragma unroll
        for (int j2 = 0; j2 < 16; j2++) {
            uint32_t vh = *(uint32_t*)(smc + SM_HBH + tid * 144 + 64 + j2 * 4);
            uint32_t vl = *(uint32_t*)(smc + SM_HBL + tid * 144 + 64 + j2 * 4);
            __nv_bfloat162 bh = *(__nv_bfloat162*)&vh, bl = *(__nv_bfloat162*)&vl;
            h1f[2 * j2]     = __bfloat162float(bh.x) + __bfloat162float(bl.x);
            h1f[2 * j2 + 1] = __bfloat162float(bh.y) + __bfloat162float(bl.y);
        }
        float y = __ldg(bfc2);
        #pragma unroll
        for (int m = 0; m < 16; m++) {
            float a = sbfc1[m];
            #pragma unroll
            for (int j = 0; j < 32; j++) a += h1f[j] * sWfc1[j * 16 + m];
            y += fmaxf(a, 0.0f) * sWfc2[m];
        }
        out[ng] = y;
    }
}

extern "C" void kernel_launch(void* const* d_in, const int* in_sizes, int n_in,
                              void* d_out, int out_size) {
    const float* x    = (const float*)d_in[0];
    // d_in[1] edge_index, d_in[2..9] GCN weights: dead code in the reference model
    const float* Wtp  = (const float*)d_in[10];
    const float* btp  = (const float*)d_in[11];
    const float* Wih0 = (const float*)d_in[12];
    const float* Whh0 = (const float*)d_in[13];
    const float* bih0 = (const float*)d_in[14];
    const float* bhh0 = (const float*)d_in[15];
    const float* Wih1 = (const float*)d_in[16];
    const float* Whh1 = (const float*)d_in[17];
    const float* bih1 = (const float*)d_in[18];
    const float* bhh1 = (const float*)d_in[19];
    const float* Wfc1 = (const float*)d_in[20];
    const float* bfc1 = (const float*)d_in[21];
    const float* Wfc2 = (const float*)d_in[22];
    const float* bfc2 = (const float*)d_in[23];
    float* out = (float*)d_out;

    cudaFuncSetAttribute(lstm_hmma_kernel,
                         cudaFuncAttributeMaxDynamicSharedMemorySize, SMEM_BYTES);

    int grid = (N_NODES + NODES_PER_CTA - 1) / NODES_PER_CTA;   // 782
    lstm_hmma_kernel<<<grid, THREADS, SMEM_BYTES>>>(
        x, Wtp, btp, Wih0, Whh0, bih0, bhh0,
        Wih1, Whh1, bih1, bhh1, Wfc1, bfc1, Wfc2, bfc2, out);
}

// round 13
// speedup vs baseline: 1.0682x; 1.0682x over previous
#include <cuda_runtime.h>
#include <cuda_bf16.h>
#include <cuda_fp16.h>
#include <cstdint>

#define N_NODES 100000
#define T_STEPS 12
#define THREADS 128

// ---------- smem byte offsets ----------
#define SM_W0A 0          // 128 rows x 80B   (Whh0 term1, K=32, pair layout)
#define SM_W0B 10240      // 128 rows x 80B   (Whh0 term2)
#define SM_W1A 20480      // 128 rows x 144B  ([Wih1|Whh1] term1, K=64)
#define SM_W1B 38912      // 128 rows x 144B  (term2)
#define SM_HB  57344      // 128 nodes x 144B (h = [h0|h1] fp16, pair layout)
#define SM_TSC 75776      // [12][128] f32
#define SM_SA0 81920      // 128 f
#define SM_SB0 82432      // 128 f
#define SM_SB1 82944      // 128 f
#define SM_FC1 83456      // 512 f
#define SM_FCB 85504      // bfc1[16] @ +0, wfc2[16] @ +64
#define SMEM_BYTES 85632  // -> 2 CTAs/SM

// ---------- helpers ----------
__device__ __forceinline__ float tanha(float x) {
    float t; asm("tanh.approx.f32 %0, %1;" : "=f"(t) : "f"(x)); return t;
}
__device__ __forceinline__ float siga(float x) { return fmaf(0.5f, tanha(0.5f * x), 0.5f); }

// pair layout: for k in [0,16) the 2-byte element goes to byte po16(k) within a
// 32B block; puts a thread's two B-fragment (or A k/k+8) regs at contiguous 8B.
__device__ __forceinline__ int po16(int k) {
    return ((k & 7) >> 1) * 8 + ((k >> 3) & 1) * 4 + (k & 1) * 2;
}
// store weight w as two fp16 terms at (row j, col k)
__device__ __forceinline__ void put2h(char* bA, char* bB, int off, float w) {
    __half h1 = __float2half_rn(w);
    __half h2 = __float2half_rn(w - __half2float(h1));
    *(uint16_t*)(bA + off) = *(uint16_t*)&h1;
    *(uint16_t*)(bB + off) = *(uint16_t*)&h2;
}
__device__ __forceinline__ uint32_t pkh2(float a, float b) {
    __half2 t = __floats2half2_rn(a, b);
    return *(uint32_t*)&t;
}
// D += A(m16k16, row) x B(k16n8, col), fp16 -> f32
__device__ __forceinline__ void mmah(float* d, const uint32_t* a, uint32_t b0, uint32_t b1) {
    asm volatile("mma.sync.aligned.m16n8k16.row.col.f32.f16.f16.f32 "
                 "{%0,%1,%2,%3}, {%4,%5,%6,%7}, {%8,%9}, {%0,%1,%2,%3};"
                 : "+f"(d[0]), "+f"(d[1]), "+f"(d[2]), "+f"(d[3])
                 : "r"(a[0]), "r"(a[1]), "r"(a[2]), "r"(a[3]), "r"(b0), "r"(b1));
}

__global__ void __launch_bounds__(THREADS)
lstm_hmma_kernel(const float* __restrict__ x,
                 const float* __restrict__ Wtp,  const float* __restrict__ btp,
                 const float* __restrict__ Wih0, const float* __restrict__ Whh0,
                 const float* __restrict__ bih0, const float* __restrict__ bhh0,
                 const float* __restrict__ Wih1, const float* __restrict__ Whh1,
                 const float* __restrict__ bih1, const float* __restrict__ bhh1,
                 const float* __restrict__ Wfc1, const float* __restrict__ bfc1,
                 const float* __restrict__ Wfc2, const float* __restrict__ bfc2,
                 float* __restrict__ out)
{
    extern __shared__ char smc[];
    float* sa0   = (float*)(smc + SM_SA0);
    float* sb0   = (float*)(smc + SM_SB0);
    float* sb1   = (float*)(smc + SM_SB1);
    float* sWfc1 = (float*)(smc + SM_FC1);
    float* sbfc1 = (float*)(smc + SM_FCB);
    float* sWfc2 = (float*)(smc + SM_FCB + 64);
    float* stsc  = (float*)(smc + SM_TSC);

    const int tid  = threadIdx.x;
    const int lane = tid & 31;
    const int warp = tid >> 5;
    const int gid  = lane >> 2;   // fragment group id (0..7)
    const int tig  = lane & 3;    // thread-in-group (0..3)
    const int NB   = warp * 32;   // this warp's node base (32 nodes/warp)

    // ---- weights -> two fp16 term tiles, pair layout ----
    for (int i = tid; i < 4096; i += THREADS) {
        int j = i >> 5, k = i & 31;
        int p = po16(k & 15);
        put2h(smc + SM_W0A, smc + SM_W0B, j * 80  + ((k >> 4) & 1) * 32 + p, Whh0[i]);
        put2h(smc + SM_W1A, smc + SM_W1B, j * 144 + (k >> 4) * 32 + p,      Wih1[i]);
        put2h(smc + SM_W1A, smc + SM_W1B, j * 144 + (2 + (k >> 4)) * 32 + p, Whh1[i]);
    }
    // folded rank-1 input projection + biases  (tid == gate row, 0..127)
    {
        float a = 0.f, b = 0.f;
        #pragma unroll
        for (int j = 0; j < 16; j++) { float w = Wih0[tid * 16 + j]; a += w * Wtp[j]; b += w * btp[j]; }
        sa0[tid] = a;
        sb0[tid] = b + bih0[tid] + bhh0[tid];
        sb1[tid] = bih1[tid] + bhh1[tid];
    }
    for (int i = tid; i < 512; i += THREADS) sWfc1[i] = Wfc1[i];
    if (tid < 16) { sbfc1[tid] = bfc1[tid]; sWfc2[tid] = Wfc2[tid]; }

    // ---- temporal inputs to smem [s][node] ----
    const int ng = blockIdx.x * THREADS + tid;
    const int nc = (ng < N_NODES) ? ng : (N_NODES - 1);
    {
        const float4* xp = (const float4*)(x + (size_t)nc * 64 + 52);
        float4 v0 = xp[0], v1 = xp[1], v2 = xp[2];
        float tv[12] = {v0.x,v0.y,v0.z,v0.w, v1.x,v1.y,v1.z,v1.w, v2.x,v2.y,v2.z,v2.w};
        #pragma unroll
        for (int s = 0; s < 12; s++) stsc[s * 128 + tid] = tv[s];
    }
    // ---- zero h tile (h0 = h1 = 0) ----
    {
        uint4 z = {0, 0, 0, 0};
        uint4* p = (uint4*)(smc + SM_HB);
        for (int i = tid; i < 1152; i += THREADS) p[i] = z;   // 18432 B
    }
    __syncthreads();

    // c-states in registers; index = (m*4 + njb)*2 + e  (m = mt*2+rh: node slot)
    float c0[32], c1[32];
    #pragma unroll
    for (int i = 0; i < 32; i++) { c0[i] = 0.f; c1[i] = 0.f; }

    #pragma unroll 1
    for (int s = 0; s < T_STEPS; s++) {
        float tscm[4];
        #pragma unroll
        for (int m = 0; m < 4; m++)
            tscm[m] = stsc[s * 128 + NB + (m >> 1) * 16 + ((m & 1) << 3) + gid];

        // ================= layer 0 : G = h0 @ Whh0^T  (K=32) =================
        uint32_t A0[2][2][4];
        #pragma unroll
        for (int mt = 0; mt < 2; mt++)
            #pragma unroll
            for (int kt = 0; kt < 2; kt++) {
                int o = (NB + mt * 16 + gid) * 144 + kt * 32 + tig * 8;
                uint2 lo = *(uint2*)(smc + SM_HB + o);
                uint2 hi = *(uint2*)(smc + SM_HB + o + 8 * 144);
                A0[mt][kt][0] = lo.x; A0[mt][kt][1] = hi.x;
                A0[mt][kt][2] = lo.y; A0[mt][kt][3] = hi.y;
            }

        #pragma unroll
        for (int njb = 0; njb < 4; njb++) {
            float D[2][4][4];
            #pragma unroll
            for (int g = 0; g < 4; g++)
                #pragma unroll
                for (int e = 0; e < 2; e++) {
                    int n = njb * 8 + g * 32 + tig * 2 + e;
                    float sa = sa0[n], sv = sb0[n];
                    #pragma unroll
                    for (int m = 0; m < 4; m++)
                        D[m >> 1][g][(m & 1) * 2 + e] = fmaf(tscm[m], sa, sv);
                }
            #pragma unroll
            for (int g = 0; g < 4; g++) {
                int nb = (njb + g * 4) * 8;
                #pragma unroll
                for (int kt = 0; kt < 2; kt++) {
                    int o = (nb + gid) * 80 + kt * 32 + tig * 8;
                    uint2 b1 = *(uint2*)(smc + SM_W0A + o);
                    uint2 b2 = *(uint2*)(smc + SM_W0B + o);
                    #pragma unroll
                    for (int mt = 0; mt < 2; mt++) {
                        mmah(D[mt][g], A0[mt][kt], b1.x, b1.y);
                        mmah(D[mt][g], A0[mt][kt], b2.x, b2.y);
                    }
                }
            }
            // epilogue: activations, c0 update, h0_new (fp16) -> HB cols 0..31
            #pragma unroll
            for (int m = 0; m < 4; m++) {
                int mt = m >> 1, rh = m & 1;
                float hv[2];
                #pragma unroll
                for (int e = 0; e < 2; e++) {
                    int idx = rh * 2 + e, ci = (m * 4 + njb) * 2 + e;
                    float cn = siga(D[mt][1][idx]) * c0[ci]
                             + siga(D[mt][0][idx]) * tanha(D[mt][2][idx]);
                    c0[ci] = cn;
                    hv[e] = siga(D[mt][3][idx]) * tanha(cn);
                }
                // k = njb*8 + tig*2 -> kt = njb>>1, po = tig*8 + (njb&1)*4
                int o = (NB + mt * 16 + rh * 8 + gid) * 144
                      + (njb >> 1) * 32 + tig * 8 + (njb & 1) * 4;
                *(uint32_t*)(smc + SM_HB + o) = pkh2(hv[0], hv[1]);
            }
        }
        __syncwarp();

        // ============ layer 1 : G = [h0new|h1] @ [Wih1|Whh1]^T  (K=64) ============
        uint32_t A1[2][4][4];
        #pragma unroll
        for (int mt = 0; mt < 2; mt++)
            #pragma unroll
            for (int kt = 0; kt < 4; kt++) {
                int o = (NB + mt * 16 + gid) * 144 + kt * 32 + tig * 8;
                uint2 lo = *(uint2*)(smc + SM_HB + o);
                uint2 hi = *(uint2*)(smc + SM_HB + o + 8 * 144);
                A1[mt][kt][0] = lo.x; A1[mt][kt][1] = hi.x;
                A1[mt][kt][2] = lo.y; A1[mt][kt][3] = hi.y;
            }

        #pragma unroll
        for (int njb = 0; njb < 4; njb++) {
            float D[2][4][4];
            #pragma unroll
            for (int g = 0; g < 4; g++)
                #pragma unroll
                for (int e = 0; e < 2; e++) {
                    float sv = sb1[njb * 8 + g * 32 + tig * 2 + e];
                    #pragma unroll
                    for (int m = 0; m < 4; m++)
                        D[m >> 1][g][(m & 1) * 2 + e] = sv;
                }
            #pragma unroll
            for (int g = 0; g < 4; g++) {
                int nb = (njb + g * 4) * 8;
                #pragma unroll
                for (int kt = 0; kt < 4; kt++) {
                    int o = (nb + gid) * 144 + kt * 32 + tig * 8;
                    uint2 b1 = *(uint2*)(smc + SM_W1A + o);
                    uint2 b2 = *(uint2*)(smc + SM_W1B + o);
                    #pragma unroll
                    for (int mt = 0; mt < 2; mt++) {
                        mmah(D[mt][g], A1[mt][kt], b1.x, b1.y);
                        mmah(D[mt][g], A1[mt][kt], b2.x, b2.y);
                    }
                }
            }
            // epilogue: activations, c1 update, h1_new (fp16) -> HB cols 32..63
            #pragma unroll
            for (int m = 0; m < 4; m++) {
                int mt = m >> 1, rh = m & 1;
                float hv[2];
                #pragma unroll
                for (int e = 0; e < 2; e++) {
                    int idx = rh * 2 + e, ci = (m * 4 + njb) * 2 + e;
                    float cn = siga(D[mt][1][idx]) * c1[ci]
                             + siga(D[mt][0][idx]) * tanha(D[mt][2][idx]);
                    c1[ci] = cn;
                    hv[e] = siga(D[mt][3][idx]) * tanha(cn);
                }
                int o = (NB + mt * 16 + rh * 8 + gid) * 144
                      + (2 + (njb >> 1)) * 32 + tig * 8 + (njb & 1) * 4;
                *(uint32_t*)(smc + SM_HB + o) = pkh2(hv[0], hv[1]);
            }
        }
        __syncwarp();
    }

    // ---- FC head: thread tid = node tid (its own warp wrote this h1) ----
    float h1f[32];
    #pragma unroll
    for (int j2 = 0; j2 < 16; j2++) {
        int u = j2 & 7;
        int o = tid * 144 + (2 + (j2 >> 3)) * 32 + (u & 3) * 8 + (u >> 2) * 4;
        uint32_t v = *(uint32_t*)(smc + SM_HB + o);
        __half2 hp = *(__half2*)&v;
        h1f[2 * j2]     = __half2float(__low2half(hp));
        h1f[2 * j2 + 1] = __half2float(__high2half(hp));
    }
    if (ng < N_NODES) {
        float y = __ldg(bfc2);
        #pragma unroll
        for (int m = 0; m < 16; m++) {
            float a = sbfc1[m];
            #pragma unroll
            for (int j = 0; j < 32; j++) a += h1f[j] * sWfc1[j * 16 + m];
            y += fmaxf(a, 0.0f) * sWfc2[m];
        }
        out[ng] = y;
    }
}

extern "C" void kernel_launch(void* const* d_in, const int* in_sizes, int n_in,
                              void* d_out, int out_size) {
    const float* x    = (const float*)d_in[0];
    // d_in[1] edge_index, d_in[2..9] GCN weights: dead code in the reference model
    const float* Wtp  = (const float*)d_in[10];
    const float* btp  = (const float*)d_in[11];
    const float* Wih0 = (const float*)d_in[12];
    const float* Whh0 = (const float*)d_in[13];
    const float* bih0 = (const float*)d_in[14];
    const float* bhh0 = (const float*)d_in[15];
    const float* Wih1 = (const float*)d_in[16];
    const float* Whh1 = (const float*)d_in[17];
    const float* bih1 = (const float*)d_in[18];
    const float* bhh1 = (const float*)d_in[19];
    const float* Wfc1 = (const float*)d_in[20];
    const float* bfc1 = (const float*)d_in[21];
    const float* Wfc2 = (const float*)d_in[22];
    const float* bfc2 = (const float*)d_in[23];
    float* out = (float*)d_out;

    cudaFuncSetAttribute(lstm_hmma_kernel,
                         cudaFuncAttributeMaxDynamicSharedMemorySize, SMEM_BYTES);

    int grid = (N_NODES + THREADS - 1) / THREADS;   // 782
    lstm_hmma_kernel<<<grid, THREADS, SMEM_BYTES>>>(
        x, Wtp, btp, Wih0, Whh0, bih0, bhh0,
        Wih1, Whh1, bih1, bhh1, Wfc1, bfc1, Wfc2, bfc2, out);
}

// round 16
// speedup vs baseline: 1.1307x; 1.0584x over previous
// R14 resubmission (R15 container failure diagnosed as infra-side; kernel has no
// hang-capable constructs — no spin waits, no mbarrier, no cross-CTA deps).
#include <cuda_runtime.h>
#include <cuda_bf16.h>
#include <cuda_fp16.h>
#include <cstdint>

#define N_NODES 100000
#define T_STEPS 12
#define THREADS 128

// ---------- smem byte offsets ----------
#define SM_W0  0          // 32 frag-blocks (jb*2+kt) x 512B   = 16384
#define SM_W1  16384      // 64 frag-blocks (jb*4+kt) x 512B   = 32768
#define SM_HB  49152      // 128 nodes x 128B fp16 [h0|h1], XOR-swizzled = 16384
#define SM_TSC 65536      // [12][128] f32 = 6144
#define SM_SA0 71680      // 128 f
#define SM_SB0 72192      // 128 f
#define SM_SB1 72704      // 128 f
#define SM_FC1 73216      // 512 f = 2048
#define SM_FCB 75264      // bfc1[16] @ +0, wfc2[16] @ +64
#define SMEM_BYTES 75392  // -> 3 CTAs/SM

// ---------- helpers ----------
__device__ __forceinline__ float tanha(float x) {
    float t; asm("tanh.approx.f32 %0, %1;" : "=f"(t) : "f"(x)); return t;
}
__device__ __forceinline__ float siga(float x) { return fmaf(0.5f, tanha(0.5f * x), 0.5f); }

// HB addressing: row n (128B), col-byte c, XOR swizzle on bits 5-6 by (n&3)
__device__ __forceinline__ int hbo(int n, int c) {
    return n * 128 + (c ^ ((n & 3) * 32));
}
// store weight w as two fp16 terms 8B apart (term1 @ base, term2 @ base+8)
__device__ __forceinline__ void put2h(char* base, float w) {
    __half h1 = __float2half_rn(w);
    __half h2 = __float2half_rn(w - __half2float(h1));
    *(uint16_t*)(base)     = *(uint16_t*)&h1;
    *(uint16_t*)(base + 8) = *(uint16_t*)&h2;
}
__device__ __forceinline__ uint32_t pkh2(float a, float b) {
    __half2 t = __floats2half2_rn(a, b);
    return *(uint32_t*)&t;
}
// D += A(m16k16, row) x B(k16n8, col), fp16 -> f32
__device__ __forceinline__ void mmah(float* d, const uint32_t* a, uint32_t b0, uint32_t b1) {
    asm volatile("mma.sync.aligned.m16n8k16.row.col.f32.f16.f16.f32 "
                 "{%0,%1,%2,%3}, {%4,%5,%6,%7}, {%8,%9}, {%0,%1,%2,%3};"
                 : "+f"(d[0]), "+f"(d[1]), "+f"(d[2]), "+f"(d[3])
                 : "r"(a[0]), "r"(a[1]), "r"(a[2]), "r"(a[3]), "r"(b0), "r"(b1));
}

__global__ void __launch_bounds__(THREADS, 3)
lstm_hmma_kernel(const float* __restrict__ x,
                 const float* __restrict__ Wtp,  const float* __restrict__ btp,
                 const float* __restrict__ Wih0, const float* __restrict__ Whh0,
                 const float* __restrict__ bih0, const float* __restrict__ bhh0,
                 const float* __restrict__ Wih1, const float* __restrict__ Whh1,
                 const float* __restrict__ bih1, const float* __restrict__ bhh1,
                 const float* __restrict__ Wfc1, const float* __restrict__ bfc1,
                 const float* __restrict__ Wfc2, const float* __restrict__ bfc2,
                 float* __restrict__ out)
{
    extern __shared__ char smc[];
    float* sa0   = (float*)(smc + SM_SA0);
    float* sb0   = (float*)(smc + SM_SB0);
    float* sb1   = (float*)(smc + SM_SB1);
    float* sWfc1 = (float*)(smc + SM_FC1);
    float* sbfc1 = (float*)(smc + SM_FCB);
    float* sWfc2 = (float*)(smc + SM_FCB + 64);
    float* stsc  = (float*)(smc + SM_TSC);

    const int tid  = threadIdx.x;
    const int lane = tid & 31;
    const int warp = tid >> 5;
    const int gid  = lane >> 2;   // fragment group id (0..7)
    const int tig  = lane & 3;    // thread-in-group (0..3)
    const int NB   = warp * 32;   // this warp's node base (32 nodes/warp)
    const int lb   = lane * 16;   // fragment byte offset within a W block

    // ---- weights -> fragment-major fp16 2-term tiles ----
    // element (j,k): block row jb=j>>3, lane = (j&7)*4 + ((k&7)>>1),
    // in-lane byte = ((k>>3)&1)*4 + (k&1)*2 (term1; term2 at +8)
    for (int i = tid; i < 4096; i += THREADS) {
        int j = i >> 5, k = i & 31;
        int jb = j >> 3, kt = k >> 4, kl = k & 15;
        int l16 = ((j & 7) * 4 + ((kl & 7) >> 1)) * 16 + ((kl >> 3) & 1) * 4 + (kl & 1) * 2;
        put2h(smc + SM_W0 + (jb * 2 + kt) * 512 + l16,       Whh0[i]);
        put2h(smc + SM_W1 + (jb * 4 + kt) * 512 + l16,       Wih1[i]);
        put2h(smc + SM_W1 + (jb * 4 + 2 + kt) * 512 + l16,   Whh1[i]);
    }
    // folded rank-1 input projection + biases  (tid == gate row, 0..127)
    {
        float a = 0.f, b = 0.f;
        #pragma unroll
        for (int j = 0; j < 16; j++) { float w = Wih0[tid * 16 + j]; a += w * Wtp[j]; b += w * btp[j]; }
        sa0[tid] = a;
        sb0[tid] = b + bih0[tid] + bhh0[tid];
        sb1[tid] = bih1[tid] + bhh1[tid];
    }
    for (int i = tid; i < 512; i += THREADS) sWfc1[i] = Wfc1[i];
    if (tid < 16) { sbfc1[tid] = bfc1[tid]; sWfc2[tid] = Wfc2[tid]; }

    // ---- temporal inputs to smem [s][node] ----
    const int ng = blockIdx.x * THREADS + tid;
    const int nc = (ng < N_NODES) ? ng : (N_NODES - 1);
    {
        const float4* xp = (const float4*)(x + (size_t)nc * 64 + 52);
        float4 v0 = xp[0], v1 = xp[1], v2 = xp[2];
        float tv[12] = {v0.x,v0.y,v0.z,v0.w, v1.x,v1.y,v1.z,v1.w, v2.x,v2.y,v2.z,v2.w};
        #pragma unroll
        for (int s = 0; s < 12; s++) stsc[s * 128 + tid] = tv[s];
    }
    // ---- zero h tile (h0 = h1 = 0) ----
    {
        uint4 z = {0, 0, 0, 0};
        uint4* p = (uint4*)(smc + SM_HB);
        for (int i = tid; i < 1024; i += THREADS) p[i] = z;   // 16384 B
    }
    __syncthreads();

    // c-states in registers; index = (m*4 + njb)*2 + e  (m = mt*2+rh)
    float c0[32], c1[32];
    #pragma unroll
    for (int i = 0; i < 32; i++) { c0[i] = 0.f; c1[i] = 0.f; }

    #pragma unroll 1
    for (int s = 0; s < T_STEPS; s++) {
        float tscm[4];
        #pragma unroll
        for (int m = 0; m < 4; m++)
            tscm[m] = stsc[s * 128 + NB + (m >> 1) * 16 + ((m & 1) << 3) + gid];

        // ================= layer 0 : G = h0 @ Whh0^T  (K=32) =================
        uint32_t A0[2][2][4];
        #pragma unroll
        for (int mt = 0; mt < 2; mt++)
            #pragma unroll
            for (int kt = 0; kt < 2; kt++) {
                int o = SM_HB + hbo(NB + mt * 16 + gid, kt * 32 + tig * 8);
                uint2 lo = *(uint2*)(smc + o);
                uint2 hi = *(uint2*)(smc + o + 1024);   // row +8, same swizzle
                A0[mt][kt][0] = lo.x; A0[mt][kt][1] = hi.x;
                A0[mt][kt][2] = lo.y; A0[mt][kt][3] = hi.y;
            }

        #pragma unroll
        for (int njb = 0; njb < 4; njb++) {
            float D[2][4][4];
            #pragma unroll
            for (int g = 0; g < 4; g++)
                #pragma unroll
                for (int e = 0; e < 2; e++) {
                    int n = njb * 8 + g * 32 + tig * 2 + e;
                    float sa = sa0[n], sv = sb0[n];
                    #pragma unroll
                    for (int m = 0; m < 4; m++)
                        D[m >> 1][g][(m & 1) * 2 + e] = fmaf(tscm[m], sa, sv);
                }
            #pragma unroll
            for (int g = 0; g < 4; g++) {
                int blk = SM_W0 + (njb + g * 4) * 1024 + lb;   // (jb*2+kt)*512
                #pragma unroll
                for (int kt = 0; kt < 2; kt++) {
                    uint4 w = *(uint4*)(smc + blk + kt * 512);
                    #pragma unroll
                    for (int mt = 0; mt < 2; mt++) {
                        mmah(D[mt][g], A0[mt][kt], w.x, w.y);
                        mmah(D[mt][g], A0[mt][kt], w.z, w.w);
                    }
                }
            }
            // epilogue: activations, c0 update, h0_new (fp16) -> HB cols 0..31
            #pragma unroll
            for (int m = 0; m < 4; m++) {
                int mt = m >> 1, rh = m & 1;
                float hv[2];
                #pragma unroll
                for (int e = 0; e < 2; e++) {
                    int idx = rh * 2 + e, ci = (m * 4 + njb) * 2 + e;
                    float cn = siga(D[mt][1][idx]) * c0[ci]
                             + siga(D[mt][0][idx]) * tanha(D[mt][2][idx]);
                    c0[ci] = cn;
                    hv[e] = siga(D[mt][3][idx]) * tanha(cn);
                }
                int n = NB + mt * 16 + rh * 8 + gid;
                int c = (njb >> 1) * 32 + tig * 8 + (njb & 1) * 4;
                *(uint32_t*)(smc + SM_HB + hbo(n, c)) = pkh2(hv[0], hv[1]);
            }
        }
        __syncwarp();

        // ============ layer 1 : G = [h0new|h1] @ [Wih1|Whh1]^T  (K=64) ============
        uint32_t A1[2][4][4];
        #pragma unroll
        for (int mt = 0; mt < 2; mt++)
            #pragma unroll
            for (int kt = 0; kt < 4; kt++) {
                int o = SM_HB + hbo(NB + mt * 16 + gid, kt * 32 + tig * 8);
                uint2 lo = *(uint2*)(smc + o);
                uint2 hi = *(uint2*)(smc + o + 1024);
                A1[mt][kt][0] = lo.x; A1[mt][kt][1] = hi.x;
                A1[mt][kt][2] = lo.y; A1[mt][kt][3] = hi.y;
            }

        #pragma unroll
        for (int njb = 0; njb < 4; njb++) {
            float D[2][4][4];
            #pragma unroll
            for (int g = 0; g < 4; g++)
                #pragma unroll
                for (int e = 0; e < 2; e++) {
                    float sv = sb1[njb * 8 + g * 32 + tig * 2 + e];
                    #pragma unroll
                    for (int m = 0; m < 4; m++)
                        D[m >> 1][g][(m & 1) * 2 + e] = sv;
                }
            #pragma unroll
            for (int g = 0; g < 4; g++) {
                int blk = SM_W1 + (njb + g * 4) * 2048 + lb;   // (jb*4+kt)*512
                #pragma unroll
                for (int kt = 0; kt < 4; kt++) {
                    uint4 w = *(uint4*)(smc + blk + kt * 512);
                    #pragma unroll
                    for (int mt = 0; mt < 2; mt++) {
                        mmah(D[mt][g], A1[mt][kt], w.x, w.y);
                        mmah(D[mt][g], A1[mt][kt], w.z, w.w);
                    }
                }
            }
            // epilogue: activations, c1 update, h1_new (fp16) -> HB cols 32..63
            #pragma unroll
            for (int m = 0; m < 4; m++) {
                int mt = m >> 1, rh = m & 1;
                float hv[2];
                #pragma unroll
                for (int e = 0; e < 2; e++) {
                    int idx = rh * 2 + e, ci = (m * 4 + njb) * 2 + e;
                    float cn = siga(D[mt][1][idx]) * c1[ci]
                             + siga(D[mt][0][idx]) * tanha(D[mt][2][idx]);
                    c1[ci] = cn;
                    hv[e] = siga(D[mt][3][idx]) * tanha(cn);
                }
                int n = NB + mt * 16 + rh * 8 + gid;
                int c = (2 + (njb >> 1)) * 32 + tig * 8 + (njb & 1) * 4;
                *(uint32_t*)(smc + SM_HB + hbo(n, c)) = pkh2(hv[0], hv[1]);
            }
        }
        __syncwarp();
    }

    // ---- FC head: thread tid = node tid (its own warp wrote this h1) ----
    float h1f[32];
    #pragma unroll
    for (int j2 = 0; j2 < 16; j2++) {
        int c = (2 + (j2 >> 3)) * 32 + (j2 & 3) * 8 + ((j2 >> 2) & 1) * 4;
        uint32_t v = *(uint32_t*)(smc + SM_HB + hbo(tid, c));
        __half2 hp = *(__half2*)&v;
        h1f[2 * j2]     = __half2float(__low2half(hp));
        h1f[2 * j2 + 1] = __half2float(__high2half(hp));
    }
    if (ng < N_NODES) {
        float y = __ldg(bfc2);
        #pragma unroll
        for (int m = 0; m < 16; m++) {
            float a = sbfc1[m];
            #pragma unroll
            for (int j = 0; j < 32; j++) a += h1f[j] * sWfc1[j * 16 + m];
            y += fmaxf(a, 0.0f) * sWfc2[m];
        }
        out[ng] = y;
    }
}

extern "C" void kernel_launch(void* const* d_in, const int* in_sizes, int n_in,
                              void* d_out, int out_size) {
    const float* x    = (const float*)d_in[0];
    // d_in[1] edge_index, d_in[2..9] GCN weights: dead code in the reference model
    const float* Wtp  = (const float*)d_in[10];
    const float* btp  = (const float*)d_in[11];
    const float* Wih0 = (const float*)d_in[12];
    const float* Whh0 = (const float*)d_in[13];
    const float* bih0 = (const float*)d_in[14];
    const float* bhh0 = (const float*)d_in[15];
    const float* Wih1 = (const float*)d_in[16];
    const float* Whh1 = (const float*)d_in[17];
    const float* bih1 = (const float*)d_in[18];
    const float* bhh1 = (const float*)d_in[19];
    const float* Wfc1 = (const float*)d_in[20];
    const float* bfc1 = (const float*)d_in[21];
    const float* Wfc2 = (const float*)d_in[22];
    const float* bfc2 = (const float*)d_in[23];
    float* out = (float*)d_out;

    cudaFuncSetAttribute(lstm_hmma_kernel,
                         cudaFuncAttributeMaxDynamicSharedMemorySize, SMEM_BYTES);

    int grid = (N_NODES + THREADS - 1) / THREADS;   // 782
    lstm_hmma_kernel<<<grid, THREADS, SMEM_BYTES>>>(
        x, Wtp, btp, Wih0, Whh0, bih0, bhh0,
        Wih1, Whh1, bih1, bhh1, Wfc1, bfc1, Wfc2, bfc2, out);
}

// round 17
// speedup vs baseline: 1.1586x; 1.0247x over previous
#include <cuda_runtime.h>
#include <cuda_bf16.h>
#include <cuda_fp16.h>
#include <cstdint>

#define N_NODES 100000
#define T_STEPS 12
#define THREADS 128

// ---------- smem byte offsets ----------
#define SM_W0  0          // 32 frag-blocks (jb*2+kt) x 512B   = 16384
#define SM_W1  16384      // 64 frag-blocks (jb*4+kt) x 512B   = 32768
#define SM_HB  49152      // 128 nodes x 128B fp16 [h0|h1], XOR-swizzled = 16384
#define SM_TSC 65536      // [12][128] f32 = 6144
#define SM_SAB 71680      // 128 x {sa0, sb0} interleaved f32 pairs = 1024
#define SM_SB1 72704      // 128 f = 512
#define SM_FC1 73216      // 512 f = 2048
#define SM_FCB 75264      // bfc1[16] @ +0, wfc2[16] @ +64
#define SMEM_BYTES 75392  // -> 3 CTAs/SM

// ---------- helpers ----------
__device__ __forceinline__ float tanha(float x) {
    float t; asm("tanh.approx.f32 %0, %1;" : "=f"(t) : "f"(x)); return t;
}
__device__ __forceinline__ float siga(float x) { return fmaf(0.5f, tanha(0.5f * x), 0.5f); }

// HB addressing: row n (128B), col-byte c, XOR swizzle on bits 5-6 by (n&3)
__device__ __forceinline__ int hbo(int n, int c) {
    return n * 128 + (c ^ ((n & 3) * 32));
}
// store weight w as two fp16 terms 8B apart (term1 @ base, term2 @ base+8)
__device__ __forceinline__ void put2h(char* base, float w) {
    __half h1 = __float2half_rn(w);
    __half h2 = __float2half_rn(w - __half2float(h1));
    *(uint16_t*)(base)     = *(uint16_t*)&h1;
    *(uint16_t*)(base + 8) = *(uint16_t*)&h2;
}
__device__ __forceinline__ uint32_t pkh2(float a, float b) {
    __half2 t = __floats2half2_rn(a, b);
    return *(uint32_t*)&t;
}
// D += A(m16k16, row) x B(k16n8, col), fp16 -> f32
__device__ __forceinline__ void mmah(float* d, const uint32_t* a, uint32_t b0, uint32_t b1) {
    asm volatile("mma.sync.aligned.m16n8k16.row.col.f32.f16.f16.f32 "
                 "{%0,%1,%2,%3}, {%4,%5,%6,%7}, {%8,%9}, {%0,%1,%2,%3};"
                 : "+f"(d[0]), "+f"(d[1]), "+f"(d[2]), "+f"(d[3])
                 : "r"(a[0]), "r"(a[1]), "r"(a[2]), "r"(a[3]), "r"(b0), "r"(b1));
}

__global__ void __launch_bounds__(THREADS, 3)
lstm_hmma_kernel(const float* __restrict__ x,
                 const float* __restrict__ Wtp,  const float* __restrict__ btp,
                 const float* __restrict__ Wih0, const float* __restrict__ Whh0,
                 const float* __restrict__ bih0, const float* __restrict__ bhh0,
                 const float* __restrict__ Wih1, const float* __restrict__ Whh1,
                 const float* __restrict__ bih1, const float* __restrict__ bhh1,
                 const float* __restrict__ Wfc1, const float* __restrict__ bfc1,
                 const float* __restrict__ Wfc2, const float* __restrict__ bfc2,
                 float* __restrict__ out)
{
    extern __shared__ char smc[];
    float* sab   = (float*)(smc + SM_SAB);
    float* sb1   = (float*)(smc + SM_SB1);
    float* sWfc1 = (float*)(smc + SM_FC1);
    float* sbfc1 = (float*)(smc + SM_FCB);
    float* sWfc2 = (float*)(smc + SM_FCB + 64);
    float* stsc  = (float*)(smc + SM_TSC);

    const int tid  = threadIdx.x;
    const int lane = tid & 31;
    const int warp = tid >> 5;
    const int gid  = lane >> 2;   // fragment group id (0..7)
    const int tig  = lane & 3;    // thread-in-group (0..3)
    const int NB   = warp * 32;   // this warp's node base (32 nodes/warp)
    const int lb   = lane * 16;   // fragment byte offset within a W block

    // ---- unified HB address registers: every A-load and epilogue store is
    // one of these 4 regs + a compile-time immediate (row: mt*2048 + rh*1024).
    const int sw  = (gid & 3) * 32;
    const int hbb = SM_HB + (NB + gid) * 128;
    const int hA0 = hbb + (((0 * 32) + tig * 8) ^ sw);
    const int hB0 = hbb + (((1 * 32) + tig * 8) ^ sw);
    const int hA1 = hbb + (((2 * 32) + tig * 8) ^ sw);
    const int hB1 = hbb + (((3 * 32) + tig * 8) ^ sw);

    // ---- weights -> fragment-major fp16 2-term tiles ----
    for (int i = tid; i < 4096; i += THREADS) {
        int j = i >> 5, k = i & 31;
        int jb = j >> 3, kt = k >> 4, kl = k & 15;
        int l16 = ((j & 7) * 4 + ((kl & 7) >> 1)) * 16 + ((kl >> 3) & 1) * 4 + (kl & 1) * 2;
        put2h(smc + SM_W0 + (jb * 2 + kt) * 512 + l16,       Whh0[i]);
        put2h(smc + SM_W1 + (jb * 4 + kt) * 512 + l16,       Wih1[i]);
        put2h(smc + SM_W1 + (jb * 4 + 2 + kt) * 512 + l16,   Whh1[i]);
    }
    // folded rank-1 input projection + biases  (tid == gate row, 0..127)
    {
        float a = 0.f, b = 0.f;
        #pragma unroll
        for (int j = 0; j < 16; j++) { float w = Wih0[tid * 16 + j]; a += w * Wtp[j]; b += w * btp[j]; }
        sab[tid * 2]     = a;
        sab[tid * 2 + 1] = b + bih0[tid] + bhh0[tid];
        sb1[tid] = bih1[tid] + bhh1[tid];
    }
    for (int i = tid; i < 512; i += THREADS) sWfc1[i] = Wfc1[i];
    if (tid < 16) { sbfc1[tid] = bfc1[tid]; sWfc2[tid] = Wfc2[tid]; }

    // ---- temporal inputs to smem [s][node] ----
    const int ng = blockIdx.x * THREADS + tid;
    const int nc = (ng < N_NODES) ? ng : (N_NODES - 1);
    {
        const float4* xp = (const float4*)(x + (size_t)nc * 64 + 52);
        float4 v0 = xp[0], v1 = xp[1], v2 = xp[2];
        float tv[12] = {v0.x,v0.y,v0.z,v0.w, v1.x,v1.y,v1.z,v1.w, v2.x,v2.y,v2.z,v2.w};
        #pragma unroll
        for (int s = 0; s < 12; s++) stsc[s * 128 + tid] = tv[s];
    }
    // ---- zero h tile (h0 = h1 = 0) ----
    {
        uint4 z = {0, 0, 0, 0};
        uint4* p = (uint4*)(smc + SM_HB);
        for (int i = tid; i < 1024; i += THREADS) p[i] = z;   // 16384 B
    }
    __syncthreads();

    // c-states in registers; index = (m*4 + njb)*2 + e  (m = mt*2+rh)
    float c0[32], c1[32];
    #pragma unroll
    for (int i = 0; i < 32; i++) { c0[i] = 0.f; c1[i] = 0.f; }

    #pragma unroll 1
    for (int s = 0; s < T_STEPS; s++) {
        float tscm[4];
        #pragma unroll
        for (int m = 0; m < 4; m++)
            tscm[m] = stsc[s * 128 + NB + (m >> 1) * 16 + ((m & 1) << 3) + gid];

        // ================= layer 0 : G = h0 @ Whh0^T  (K=32) =================
        uint32_t A0[2][2][4];
        #pragma unroll
        for (int mt = 0; mt < 2; mt++)
            #pragma unroll
            for (int kt = 0; kt < 2; kt++) {
                const int o = (kt ? hB0 : hA0) + mt * 2048;
                uint2 lo = *(uint2*)(smc + o);
                uint2 hi = *(uint2*)(smc + o + 1024);   // row +8, same swizzle
                A0[mt][kt][0] = lo.x; A0[mt][kt][1] = hi.x;
                A0[mt][kt][2] = lo.y; A0[mt][kt][3] = hi.y;
            }

        uint32_t sprev[4];
        #pragma unroll
        for (int njb = 0; njb < 4; njb++) {
            float D[2][4][4];
            #pragma unroll
            for (int g = 0; g < 4; g++) {
                const float4 q = *(const float4*)(smc + SM_SAB + (njb * 8 + g * 32 + tig * 2) * 8);
                #pragma unroll
                for (int m = 0; m < 4; m++) {
                    D[m >> 1][g][(m & 1) * 2 + 0] = fmaf(tscm[m], q.x, q.y);
                    D[m >> 1][g][(m & 1) * 2 + 1] = fmaf(tscm[m], q.z, q.w);
                }
            }
            #pragma unroll
            for (int g = 0; g < 4; g++) {
                int blk = SM_W0 + (njb + g * 4) * 1024 + lb;   // (jb*2+kt)*512
                #pragma unroll
                for (int kt = 0; kt < 2; kt++) {
                    uint4 w = *(uint4*)(smc + blk + kt * 512);
                    #pragma unroll
                    for (int mt = 0; mt < 2; mt++) {
                        mmah(D[mt][g], A0[mt][kt], w.x, w.y);
                        mmah(D[mt][g], A0[mt][kt], w.z, w.w);
                    }
                }
            }
            // epilogue: activations, c0 update, h0_new (fp16) buffered to STS.64
            #pragma unroll
            for (int m = 0; m < 4; m++) {
                int mt = m >> 1, rh = m & 1;
                float hv[2];
                #pragma unroll
                for (int e = 0; e < 2; e++) {
                    int idx = rh * 2 + e, ci = (m * 4 + njb) * 2 + e;
                    float cn = siga(D[mt][1][idx]) * c0[ci]
                             + siga(D[mt][0][idx]) * tanha(D[mt][2][idx]);
                    c0[ci] = cn;
                    hv[e] = siga(D[mt][3][idx]) * tanha(cn);
                }
                uint32_t pv = pkh2(hv[0], hv[1]);
                if (njb & 1) {
                    const int addr = ((njb == 1) ? hA0 : hB0) + mt * 2048 + rh * 1024;
                    *(uint2*)(smc + addr) = make_uint2(sprev[m], pv);
                } else {
                    sprev[m] = pv;
                }
            }
        }
        __syncwarp();

        // ============ layer 1 : G = [h0new|h1] @ [Wih1|Whh1]^T  (K=64) ============
        uint32_t A1[2][4][4];
        #pragma unroll
        for (int mt = 0; mt < 2; mt++) {
            #pragma unroll
            for (int kt = 0; kt < 4; kt++) {
                const int hx = (kt == 0) ? hA0 : (kt == 1) ? hB0 : (kt == 2) ? hA1 : hB1;
                const int o = hx + mt * 2048;
                uint2 lo = *(uint2*)(smc + o);
                uint2 hi = *(uint2*)(smc + o + 1024);
                A1[mt][kt][0] = lo.x; A1[mt][kt][1] = hi.x;
                A1[mt][kt][2] = lo.y; A1[mt][kt][3] = hi.y;
            }
        }

        #pragma unroll
        for (int njb = 0; njb < 4; njb++) {
            float D[2][4][4];
            #pragma unroll
            for (int g = 0; g < 4; g++) {
                const float2 v = *(const float2*)(&sb1[njb * 8 + g * 32 + tig * 2]);
                #pragma unroll
                for (int m = 0; m < 4; m++) {
                    D[m >> 1][g][(m & 1) * 2 + 0] = v.x;
                    D[m >> 1][g][(m & 1) * 2 + 1] = v.y;
                }
            }
            #pragma unroll
            for (int g = 0; g < 4; g++) {
                int blk = SM_W1 + (njb + g * 4) * 2048 + lb;   // (jb*4+kt)*512
                #pragma unroll
                for (int kt = 0; kt < 4; kt++) {
                    uint4 w = *(uint4*)(smc + blk + kt * 512);
                    #pragma unroll
                    for (int mt = 0; mt < 2; mt++) {
                        mmah(D[mt][g], A1[mt][kt], w.x, w.y);
                        mmah(D[mt][g], A1[mt][kt], w.z, w.w);
                    }
                }
            }
            // epilogue: activations, c1 update, h1_new (fp16) buffered to STS.64
            #pragma unroll
            for (int m = 0; m < 4; m++) {
                int mt = m >> 1, rh = m & 1;
                float hv[2];
                #pragma unroll
                for (int e = 0; e < 2; e++) {
                    int idx = rh * 2 + e, ci = (m * 4 + njb) * 2 + e;
                    float cn = siga(D[mt][1][idx]) * c1[ci]
                             + siga(D[mt][0][idx]) * tanha(D[mt][2][idx]);
                    c1[ci] = cn;
                    hv[e] = siga(D[mt][3][idx]) * tanha(cn);
                }
                uint32_t pv = pkh2(hv[0], hv[1]);
                if (njb & 1) {
                    const int addr = ((njb == 1) ? hA1 : hB1) + mt * 2048 + rh * 1024;
                    *(uint2*)(smc + addr) = make_uint2(sprev[m], pv);
                } else {
                    sprev[m] = pv;
                }
            }
        }
        __syncwarp();
    }

    // ---- FC head: thread tid = node tid (its own warp wrote this h1) ----
    float h1f[32];
    #pragma unroll
    for (int j2 = 0; j2 < 16; j2++) {
        int c = (2 + (j2 >> 3)) * 32 + (j2 & 3) * 8 + ((j2 >> 2) & 1) * 4;
        uint32_t v = *(uint32_t*)(smc + SM_HB + hbo(tid, c));
        __half2 hp = *(__half2*)&v;
        h1f[2 * j2]     = __half2float(__low2half(hp));
        h1f[2 * j2 + 1] = __half2float(__high2half(hp));
    }
    if (ng < N_NODES) {
        float y = __ldg(bfc2);
        #pragma unroll
        for (int m = 0; m < 16; m++) {
            float a = sbfc1[m];
            #pragma unroll
            for (int j = 0; j < 32; j++) a += h1f[j] * sWfc1[j * 16 + m];
            y += fmaxf(a, 0.0f) * sWfc2[m];
        }
        out[ng] = y;
    }
}

extern "C" void kernel_launch(void* const* d_in, const int* in_sizes, int n_in,
                              void* d_out, int out_size) {
    const float* x    = (const float*)d_in[0];
    // d_in[1] edge_index, d_in[2..9] GCN weights: dead code in the reference model
    const float* Wtp  = (const float*)d_in[10];
    const float* btp  = (const float*)d_in[11];
    const float* Wih0 = (const float*)d_in[12];
    const float* Whh0 = (const float*)d_in[13];
    const float* bih0 = (const float*)d_in[14];
    const float* bhh0 = (const float*)d_in[15];
    const float* Wih1 = (const float*)d_in[16];
    const float* Whh1 = (const float*)d_in[17];
    const float* bih1 = (const float*)d_in[18];
    const float* bhh1 = (const float*)d_in[19];
    const float* Wfc1 = (const float*)d_in[20];
    const float* bfc1 = (const float*)d_in[21];
    const float* Wfc2 = (const float*)d_in[22];
    const float* bfc2 = (const float*)d_in[23];
    float* out = (float*)d_out;

    cudaFuncSetAttribute(lstm_hmma_kernel,
                         cudaFuncAttributeMaxDynamicSharedMemorySize, SMEM_BYTES);

    int grid = (N_NODES + THREADS - 1) / THREADS;   // 782
    lstm_hmma_kernel<<<grid, THREADS, SMEM_BYTES>>>(
        x, Wtp, btp, Wih0, Whh0, bih0, bhh0,
        Wih1, Whh1, bih1, bhh1, Wfc1, bfc1, Wfc2, bfc2, out);
}